// round 5
// baseline (speedup 1.0000x reference)
#include <cuda_runtime.h>

#define CK_B 64
#define CK_P 12
#define CK_Q 12
#define CK_N 1024
#define CK_D 64
#define CK_BN (CK_B*CK_N)   // 65536 rows

// Scratch: [t][b][n][d]. Xe written here, layer1 overwrites in place with seq1.
__device__ float g_buf[(size_t)CK_P * CK_BN * CK_D];
__device__ float g_se2[CK_N * CK_D];
__device__ float g_te2[CK_B * CK_P * CK_D];
// Folded weights: Weff[k][j] = W[k][j] + W[k+128][j]  (support == identity)
__device__ float g_Wg1[128 * 128];
__device__ float g_Wc1[128 * 64];
__device__ float g_Wg2[128 * 128];
__device__ float g_Wc2[128 * 64];

__device__ __forceinline__ float sigm(float x) {
    return __fdividef(1.0f, 1.0f + __expf(-x));
}
__device__ __forceinline__ float tanh_f(float x) {
    return __fdividef(2.0f, 1.0f + __expf(-2.0f * x)) - 1.0f;
}

// ---------------------------------------------------------------- weight fold
__global__ void fold_k(const float* __restrict__ Wg1, const float* __restrict__ Wc1,
                       const float* __restrict__ Wg2, const float* __restrict__ Wc2) {
    int i = blockIdx.x * 256 + threadIdx.x;
    if (i < 128 * 128) {
        g_Wg1[i] = Wg1[i] + Wg1[i + 128 * 128];
        g_Wg2[i] = Wg2[i] + Wg2[i + 128 * 128];
    }
    if (i < 128 * 64) {
        g_Wc1[i] = Wc1[i] + Wc1[i + 128 * 64];
        g_Wc2[i] = Wc2[i] + Wc2[i + 128 * 64];
    }
}

// ---------------------------------------------------------------- SE embedding
__global__ void se_k(const float* __restrict__ SE, const float* __restrict__ W1,
                     const float* __restrict__ b1, const float* __restrict__ W2,
                     const float* __restrict__ b2) {
    __shared__ float srow[64];
    __shared__ float h[64];
    int n = blockIdx.x, d = threadIdx.x;
    srow[d] = SE[n * 64 + d];
    __syncthreads();
    float a = b1[d];
#pragma unroll 16
    for (int k = 0; k < 64; k++) a = fmaf(srow[k], W1[k * 64 + d], a);
    h[d] = fmaxf(a, 0.f);
    __syncthreads();
    float o = b2[d];
#pragma unroll 16
    for (int k = 0; k < 64; k++) o = fmaf(h[k], W2[k * 64 + d], o);
    g_se2[n * 64 + d] = o;
}

// ---------------------------------------------------------------- TE embedding
__global__ void te_k(const int* __restrict__ TE, const float* __restrict__ W1,
                     const float* __restrict__ b1, const float* __restrict__ W2,
                     const float* __restrict__ b2) {
    __shared__ float h[64];
    int bp = blockIdx.x;          // b*12 + p
    int b = bp / 12, p = bp % 12, d = threadIdx.x;
    int dow = TE[(b * 24 + p) * 2 + 0];
    int tod = TE[(b * 24 + p) * 2 + 1];
    float a = W1[dow * 64 + d] + W1[(7 + tod) * 64 + d] + b1[d];
    h[d] = fmaxf(a, 0.f);
    __syncthreads();
    float o = b2[d];
#pragma unroll 16
    for (int k = 0; k < 64; k++) o = fmaf(h[k], W2[k * 64 + d], o);
    g_te2[bp * 64 + d] = o;
}

// ---------------------------------------------------------------- FC_X_in + STE
__global__ void xe_k(const float* __restrict__ X, const float* __restrict__ W1,
                     const float* __restrict__ b1, const float* __restrict__ W2,
                     const float* __restrict__ b2) {
    __shared__ float sW2[64 * 64];
    __shared__ float sw1[64], sb1[64], sb2[64];
    int tid = threadIdx.x;  // 128
    for (int i = tid; i < 4096; i += 128) sW2[i] = W2[i];
    if (tid < 64) { sw1[tid] = W1[tid]; sb1[tid] = b1[tid]; sb2[tid] = b2[tid]; }
    __syncthreads();

    int pos = blockIdx.x * 128 + tid;       // (t,b,n) flattened, g_buf order
    int t = pos / CK_BN;
    int r = pos - t * CK_BN;
    int b = r >> 10;
    int n = r & 1023;
    float x = X[(b * CK_P + t) * CK_N + n];

    float acc[64];
#pragma unroll
    for (int j = 0; j < 64; j++) acc[j] = 0.f;
#pragma unroll 8
    for (int d = 0; d < 64; d++) {
        float hv = fmaxf(fmaf(x, sw1[d], sb1[d]), 0.f);
        const float4* wr = (const float4*)(sW2 + d * 64);
#pragma unroll
        for (int j4 = 0; j4 < 16; j4++) {
            float4 w = wr[j4];
            acc[j4 * 4 + 0] = fmaf(hv, w.x, acc[j4 * 4 + 0]);
            acc[j4 * 4 + 1] = fmaf(hv, w.y, acc[j4 * 4 + 1]);
            acc[j4 * 4 + 2] = fmaf(hv, w.z, acc[j4 * 4 + 2]);
            acc[j4 * 4 + 3] = fmaf(hv, w.w, acc[j4 * 4 + 3]);
        }
    }
    const float* se = g_se2 + n * 64;
    const float* te = g_te2 + (b * CK_P + t) * 64;
    float* outp = g_buf + (size_t)pos * 64;
#pragma unroll
    for (int j4 = 0; j4 < 16; j4++) {
        float4 v;
        v.x = acc[j4 * 4 + 0] + sb2[j4 * 4 + 0] + se[j4 * 4 + 0] + te[j4 * 4 + 0];
        v.y = acc[j4 * 4 + 1] + sb2[j4 * 4 + 1] + se[j4 * 4 + 1] + te[j4 * 4 + 1];
        v.z = acc[j4 * 4 + 2] + sb2[j4 * 4 + 2] + se[j4 * 4 + 2] + te[j4 * 4 + 2];
        v.w = acc[j4 * 4 + 3] + sb2[j4 * 4 + 3] + se[j4 * 4 + 3] + te[j4 * 4 + 3];
        *(float4*)(outp + j4 * 4) = v;
    }
}

// ---------------------------------------------------------------- DCGRU layer
// Persistent per-tile scan: block owns 64 rows, runs all 12 time steps with
// weights + state resident in SMEM. LAYER selects folded weights; FINAL adds
// the output FC epilogue (layer 2) instead of writing the sequence.
#define GFMA(aa, i)                                                           \
    acc[i][0] = fmaf(aa, w0.x, acc[i][0]); acc[i][1] = fmaf(aa, w0.y, acc[i][1]); \
    acc[i][2] = fmaf(aa, w0.z, acc[i][2]); acc[i][3] = fmaf(aa, w0.w, acc[i][3]); \
    acc[i][4] = fmaf(aa, w1.x, acc[i][4]); acc[i][5] = fmaf(aa, w1.y, acc[i][5]); \
    acc[i][6] = fmaf(aa, w1.z, acc[i][6]); acc[i][7] = fmaf(aa, w1.w, acc[i][7]);

#define CFMA(aa, i)                                                             \
    acc2[i][0] = fmaf(aa, w.x, acc2[i][0]); acc2[i][1] = fmaf(aa, w.y, acc2[i][1]); \
    acc2[i][2] = fmaf(aa, w.z, acc2[i][2]); acc2[i][3] = fmaf(aa, w.w, acc2[i][3]);

template<int LAYER, bool FINAL>
__global__ void __launch_bounds__(512, 1) gru_k(
        const float* __restrict__ bg, const float* __restrict__ bc,
        const float* __restrict__ Wo1, const float* __restrict__ bo1,
        const float* __restrict__ Wo2, const float* __restrict__ bo2,
        float* __restrict__ out) {
    extern __shared__ float sm[];
    float* sWg  = sm;            // [128][128]
    float* sWc  = sWg + 16384;   // [128][64]
    float* sZt  = sWc + 8192;    // [128][64]  k-major: rows 0..63 = x_t, 64..127 = r*s
    float* sSt  = sZt + 8192;    // [64][64]   state, k-major
    float* sU   = sSt + 4096;    // [64][64]   update gate
    float* sbg  = sU + 4096;     // 128
    float* sbc  = sbg + 128;     // 64
    float* sWo1 = sbc + 64;      // [64][64]
    float* sWo2 = sWo1 + 4096;   // [64][12]
    float* sbo1 = sWo2 + 768;    // 64
    float* sbo2 = sbo1 + 64;     // 12

    const float* Wg = (LAYER == 0) ? g_Wg1 : g_Wg2;
    const float* Wc = (LAYER == 0) ? g_Wc1 : g_Wc2;

    int tid = threadIdx.x;  // 512
    for (int i = tid; i < 16384; i += 512) sWg[i] = Wg[i];
    for (int i = tid; i < 8192; i += 512)  sWc[i] = Wc[i];
    for (int i = tid; i < 4096; i += 512)  sSt[i] = 0.f;
    if (tid < 128) sbg[tid] = bg[tid];
    if (tid < 64)  sbc[tid] = bc[tid];
    if (FINAL) {
        for (int i = tid; i < 4096; i += 512) sWo1[i] = Wo1[i];
        for (int i = tid; i < 768; i += 512)  sWo2[i] = Wo2[i];   // FIX: was `if (tid<768)` with 512 threads -> rows 42..63 garbage
        if (tid < 64)  sbo1[tid] = bo1[tid];
        if (tid < 12)  sbo2[tid] = bo2[tid];
    }
    __syncthreads();

    int row0 = blockIdx.x * 64;
    int tr = tid >> 4;   // 0..31 -> rows tr*2, tr*2+1
    int tc = tid & 15;   // 0..15
    int r0 = tr * 2;

    for (int t = 0; t < CK_P; t++) {
        // load x_t transposed into sZt[k][row]
        const float* src = g_buf + ((size_t)t * CK_BN + row0) * 64;
        for (int it = tid; it < 1024; it += 512) {
            int rr = it >> 4;
            int d4 = (it & 15) * 4;
            float4 v = *(const float4*)(src + rr * 64 + d4);
            sZt[(d4 + 0) * 64 + rr] = v.x;
            sZt[(d4 + 1) * 64 + rr] = v.y;
            sZt[(d4 + 2) * 64 + rr] = v.z;
            sZt[(d4 + 3) * 64 + rr] = v.w;
        }
        __syncthreads();

        // gate GEMM: [64 rows x 128 cols], K = 128 ( = [x | s] )
        float acc[2][8];
#pragma unroll
        for (int j = 0; j < 8; j++) { float bv = sbg[tc * 8 + j]; acc[0][j] = bv; acc[1][j] = bv; }
        {
            const float* aX = sZt + r0;
            const float* bW = sWg + tc * 8;
#pragma unroll 8
            for (int k = 0; k < 64; k++) {
                float2 a = *(const float2*)(aX + k * 64);
                float4 w0 = *(const float4*)(bW + k * 128);
                float4 w1 = *(const float4*)(bW + k * 128 + 4);
                GFMA(a.x, 0)
                GFMA(a.y, 1)
            }
            const float* aS = sSt + r0;
            const float* bW2 = sWg + 64 * 128 + tc * 8;
#pragma unroll 8
            for (int k = 0; k < 64; k++) {
                float2 a = *(const float2*)(aS + k * 64);
                float4 w0 = *(const float4*)(bW2 + k * 128);
                float4 w1 = *(const float4*)(bW2 + k * 128 + 4);
                GFMA(a.x, 0)
                GFMA(a.y, 1)
            }
        }
        // sigmoid; cols 0..63 = r -> stage r*s into sZt bottom; cols 64..127 = u -> sU
        if (tc < 8) {
#pragma unroll
            for (int i = 0; i < 2; i++)
#pragma unroll
                for (int j = 0; j < 8; j++) {
                    int col = tc * 8 + j, row = r0 + i;
                    float rv = sigm(acc[i][j]);
                    sZt[(64 + col) * 64 + row] = rv * sSt[col * 64 + row];
                }
        } else {
#pragma unroll
            for (int i = 0; i < 2; i++)
#pragma unroll
                for (int j = 0; j < 8; j++) {
                    int col = tc * 8 + j - 64, row = r0 + i;
                    sU[col * 64 + row] = sigm(acc[i][j]);
                }
        }
        __syncthreads();

        // candidate GEMM: [64 x 64], K = 128 ( = [x | r*s] )
        float acc2[2][4];
#pragma unroll
        for (int j = 0; j < 4; j++) { float bv = sbc[tc * 4 + j]; acc2[0][j] = bv; acc2[1][j] = bv; }
        {
            const float* aZ = sZt + r0;
            const float* bC = sWc + tc * 4;
#pragma unroll 8
            for (int k = 0; k < 128; k++) {
                float2 a = *(const float2*)(aZ + k * 64);
                float4 w = *(const float4*)(bC + k * 64);
                CFMA(a.x, 0)
                CFMA(a.y, 1)
            }
        }
        // state update: new = c + u*(s - c)
#pragma unroll
        for (int i = 0; i < 2; i++) {
            int row = r0 + i;
            float4 nv;
            float* nvp = &nv.x;
#pragma unroll
            for (int j = 0; j < 4; j++) {
                int col = tc * 4 + j;
                float cv = tanh_f(acc2[i][j]);
                float u = sU[col * 64 + row];
                float s = sSt[col * 64 + row];
                float v = fmaf(u, s - cv, cv);
                sSt[col * 64 + row] = v;
                nvp[j] = v;
            }
            if (!FINAL) {
                *(float4*)(g_buf + ((size_t)t * CK_BN + row0 + row) * 64 + tc * 4) = nv;
            }
        }
        __syncthreads();
    }

    if (FINAL) {
        // o1 = relu(h @ Wo1 + bo1): [64 x 64], K = 64
        float acc2[2][4];
#pragma unroll
        for (int j = 0; j < 4; j++) { float bv = sbo1[tc * 4 + j]; acc2[0][j] = bv; acc2[1][j] = bv; }
        {
            const float* aS = sSt + r0;
            const float* bC = sWo1 + tc * 4;
#pragma unroll 8
            for (int k = 0; k < 64; k++) {
                float2 a = *(const float2*)(aS + k * 64);
                float4 w = *(const float4*)(bC + k * 64);
                CFMA(a.x, 0)
                CFMA(a.y, 1)
            }
        }
#pragma unroll
        for (int i = 0; i < 2; i++)
#pragma unroll
            for (int j = 0; j < 4; j++)
                sZt[(tc * 4 + j) * 64 + (r0 + i)] = fmaxf(acc2[i][j], 0.f);
        __syncthreads();

        // y = o1 @ Wo2 + bo2 -> out[b][q][n]
        for (int idx = tid; idx < 64 * 12; idx += 512) {
            int row = idx / 12, q = idx % 12;
            float a = sbo2[q];
#pragma unroll 16
            for (int k = 0; k < 64; k++) a = fmaf(sZt[k * 64 + row], sWo2[k * 12 + q], a);
            int rowg = row0 + row;
            int b = rowg >> 10, n = rowg & 1023;
            out[((size_t)b * CK_Q + q) * CK_N + n] = a;
        }
    }
}

// ---------------------------------------------------------------- launch
extern "C" void kernel_launch(void* const* d_in, const int* in_sizes, int n_in,
                              void* d_out, int out_size) {
    const float* X     = (const float*)d_in[0];
    const float* SE    = (const float*)d_in[3];
    const float* W_se1 = (const float*)d_in[4];
    const float* b_se1 = (const float*)d_in[5];
    const float* W_se2 = (const float*)d_in[6];
    const float* b_se2 = (const float*)d_in[7];
    const float* W_te1 = (const float*)d_in[8];
    const float* b_te1 = (const float*)d_in[9];
    const float* W_te2 = (const float*)d_in[10];
    const float* b_te2 = (const float*)d_in[11];
    const float* W_in1 = (const float*)d_in[12];
    const float* b_in1 = (const float*)d_in[13];
    const float* W_in2 = (const float*)d_in[14];
    const float* b_in2 = (const float*)d_in[15];
    const float* Wg1   = (const float*)d_in[16];
    const float* bg1   = (const float*)d_in[17];
    const float* Wc1   = (const float*)d_in[18];
    const float* bc1   = (const float*)d_in[19];
    const float* Wg2   = (const float*)d_in[20];
    const float* bg2   = (const float*)d_in[21];
    const float* Wc2   = (const float*)d_in[22];
    const float* bc2   = (const float*)d_in[23];
    const float* W_o1  = (const float*)d_in[24];
    const float* b_o1  = (const float*)d_in[25];
    const float* W_o2  = (const float*)d_in[26];
    const float* b_o2  = (const float*)d_in[27];
    const int*   TE    = (const int*)d_in[28];
    float* out = (float*)d_out;

    size_t smem = (size_t)(16384 + 8192 + 8192 + 4096 + 4096 + 128 + 64 +
                           4096 + 768 + 64 + 16) * sizeof(float);
    cudaFuncSetAttribute(gru_k<0, false>, cudaFuncAttributeMaxDynamicSharedMemorySize, (int)smem);
    cudaFuncSetAttribute(gru_k<1, true>,  cudaFuncAttributeMaxDynamicSharedMemorySize, (int)smem);

    fold_k<<<64, 256>>>(Wg1, Wc1, Wg2, Wc2);
    se_k<<<CK_N, 64>>>(SE, W_se1, b_se1, W_se2, b_se2);
    te_k<<<CK_B * CK_P, 64>>>(TE, W_te1, b_te1, W_te2, b_te2);
    xe_k<<<(CK_P * CK_BN) / 128, 128>>>(X, W_in1, b_in1, W_in2, b_in2);
    gru_k<0, false><<<CK_BN / 64, 512, smem>>>(bg1, bc1, nullptr, nullptr, nullptr, nullptr, nullptr);
    gru_k<1, true><<<CK_BN / 64, 512, smem>>>(bg2, bc2, W_o1, b_o1, W_o2, b_o2, out);
}

// round 7
// speedup vs baseline: 1.5520x; 1.5520x over previous
#include <cuda_runtime.h>

#define CK_B 64
#define CK_P 12
#define CK_Q 12
#define CK_N 1024
#define CK_D 64
#define CK_BN (CK_B*CK_N)   // 65536 rows

// Scratch: [t][b][n][d]. Xe written here, layer1 overwrites in place with seq1.
__device__ float g_buf[(size_t)CK_P * CK_BN * CK_D];
__device__ float g_se2[CK_N * CK_D];
__device__ float g_te2[CK_B * CK_P * CK_D];
// Folded weights: Weff[k][j] = W[k][j] + W[k+128][j]  (support == identity)
__device__ float g_Wg1[128 * 128];
__device__ float g_Wc1[128 * 64];
__device__ float g_Wg2[128 * 128];
__device__ float g_Wc2[128 * 64];

__device__ __forceinline__ float sigm(float x) {
    return __fdividef(1.0f, 1.0f + __expf(-x));
}
__device__ __forceinline__ float tanh_f(float x) {
    return __fdividef(2.0f, 1.0f + __expf(-2.0f * x)) - 1.0f;
}

// ---------------------------------------------------------------- weight fold
__global__ void fold_k(const float* __restrict__ Wg1, const float* __restrict__ Wc1,
                       const float* __restrict__ Wg2, const float* __restrict__ Wc2) {
    int i = blockIdx.x * 256 + threadIdx.x;
    if (i < 128 * 128) {
        g_Wg1[i] = Wg1[i] + Wg1[i + 128 * 128];
        g_Wg2[i] = Wg2[i] + Wg2[i + 128 * 128];
    }
    if (i < 128 * 64) {
        g_Wc1[i] = Wc1[i] + Wc1[i + 128 * 64];
        g_Wc2[i] = Wc2[i] + Wc2[i + 128 * 64];
    }
}

// ---------------------------------------------------------------- SE embedding
__global__ void se_k(const float* __restrict__ SE, const float* __restrict__ W1,
                     const float* __restrict__ b1, const float* __restrict__ W2,
                     const float* __restrict__ b2) {
    __shared__ float srow[64];
    __shared__ float h[64];
    int n = blockIdx.x, d = threadIdx.x;
    srow[d] = SE[n * 64 + d];
    __syncthreads();
    float a = b1[d];
#pragma unroll 16
    for (int k = 0; k < 64; k++) a = fmaf(srow[k], W1[k * 64 + d], a);
    h[d] = fmaxf(a, 0.f);
    __syncthreads();
    float o = b2[d];
#pragma unroll 16
    for (int k = 0; k < 64; k++) o = fmaf(h[k], W2[k * 64 + d], o);
    g_se2[n * 64 + d] = o;
}

// ---------------------------------------------------------------- TE embedding
__global__ void te_k(const int* __restrict__ TE, const float* __restrict__ W1,
                     const float* __restrict__ b1, const float* __restrict__ W2,
                     const float* __restrict__ b2) {
    __shared__ float h[64];
    int bp = blockIdx.x;          // b*12 + p
    int b = bp / 12, p = bp % 12, d = threadIdx.x;
    int dow = TE[(b * 24 + p) * 2 + 0];
    int tod = TE[(b * 24 + p) * 2 + 1];
    float a = W1[dow * 64 + d] + W1[(7 + tod) * 64 + d] + b1[d];
    h[d] = fmaxf(a, 0.f);
    __syncthreads();
    float o = b2[d];
#pragma unroll 16
    for (int k = 0; k < 64; k++) o = fmaf(h[k], W2[k * 64 + d], o);
    g_te2[bp * 64 + d] = o;
}

// ---------------------------------------------------------------- FC_X_in + STE
__global__ void xe_k(const float* __restrict__ X, const float* __restrict__ W1,
                     const float* __restrict__ b1, const float* __restrict__ W2,
                     const float* __restrict__ b2) {
    __shared__ float sW2[64 * 64];
    __shared__ float sw1[64], sb1[64], sb2[64];
    int tid = threadIdx.x;  // 128
    for (int i = tid; i < 4096; i += 128) sW2[i] = W2[i];
    if (tid < 64) { sw1[tid] = W1[tid]; sb1[tid] = b1[tid]; sb2[tid] = b2[tid]; }
    __syncthreads();

    int pos = blockIdx.x * 128 + tid;       // (t,b,n) flattened, g_buf order
    int t = pos / CK_BN;
    int r = pos - t * CK_BN;
    int b = r >> 10;
    int n = r & 1023;
    float x = X[(b * CK_P + t) * CK_N + n];

    float acc[64];
#pragma unroll
    for (int j = 0; j < 64; j++) acc[j] = 0.f;
#pragma unroll 8
    for (int d = 0; d < 64; d++) {
        float hv = fmaxf(fmaf(x, sw1[d], sb1[d]), 0.f);
        const float4* wr = (const float4*)(sW2 + d * 64);
#pragma unroll
        for (int j4 = 0; j4 < 16; j4++) {
            float4 w = wr[j4];
            acc[j4 * 4 + 0] = fmaf(hv, w.x, acc[j4 * 4 + 0]);
            acc[j4 * 4 + 1] = fmaf(hv, w.y, acc[j4 * 4 + 1]);
            acc[j4 * 4 + 2] = fmaf(hv, w.z, acc[j4 * 4 + 2]);
            acc[j4 * 4 + 3] = fmaf(hv, w.w, acc[j4 * 4 + 3]);
        }
    }
    const float* se = g_se2 + n * 64;
    const float* te = g_te2 + (b * CK_P + t) * 64;
    float* outp = g_buf + (size_t)pos * 64;
#pragma unroll
    for (int j4 = 0; j4 < 16; j4++) {
        float4 v;
        v.x = acc[j4 * 4 + 0] + sb2[j4 * 4 + 0] + se[j4 * 4 + 0] + te[j4 * 4 + 0];
        v.y = acc[j4 * 4 + 1] + sb2[j4 * 4 + 1] + se[j4 * 4 + 1] + te[j4 * 4 + 1];
        v.z = acc[j4 * 4 + 2] + sb2[j4 * 4 + 2] + se[j4 * 4 + 2] + te[j4 * 4 + 2];
        v.w = acc[j4 * 4 + 3] + sb2[j4 * 4 + 3] + se[j4 * 4 + 3] + te[j4 * 4 + 3];
        *(float4*)(outp + j4 * 4) = v;
    }
}

// ---------------------------------------------------------------- DCGRU layer
// Persistent per-tile scan: block owns 64 rows, runs all 12 time steps with
// weights + state resident in SMEM. LAYER selects folded weights; FINAL adds
// the output FC epilogue (layer 2) instead of writing the sequence.
#define GFMA(aa, i)                                                           \
    acc[i][0] = fmaf(aa, w0.x, acc[i][0]); acc[i][1] = fmaf(aa, w0.y, acc[i][1]); \
    acc[i][2] = fmaf(aa, w0.z, acc[i][2]); acc[i][3] = fmaf(aa, w0.w, acc[i][3]); \
    acc[i][4] = fmaf(aa, w1.x, acc[i][4]); acc[i][5] = fmaf(aa, w1.y, acc[i][5]); \
    acc[i][6] = fmaf(aa, w1.z, acc[i][6]); acc[i][7] = fmaf(aa, w1.w, acc[i][7]);

#define CFMA(aa, i)                                                             \
    acc2[i][0] = fmaf(aa, w.x, acc2[i][0]); acc2[i][1] = fmaf(aa, w.y, acc2[i][1]); \
    acc2[i][2] = fmaf(aa, w.z, acc2[i][2]); acc2[i][3] = fmaf(aa, w.w, acc2[i][3]);

template<int LAYER, bool FINAL>
__global__ void __launch_bounds__(512, 1) gru_k(
        const float* __restrict__ bg, const float* __restrict__ bc,
        const float* __restrict__ Wo1, const float* __restrict__ bo1,
        const float* __restrict__ Wo2, const float* __restrict__ bo2,
        float* __restrict__ out) {
    extern __shared__ float sm[];
    float* sWg  = sm;            // [128][128]
    float* sWc  = sWg + 16384;   // [128][64]
    float* sZt  = sWc + 8192;    // [128][64]  k-major: rows 0..63 = x_t, 64..127 = r*s
    float* sSt  = sZt + 8192;    // [64][64]   state, k-major
    float* sU   = sSt + 4096;    // [64][64]   update gate
    float* sbg  = sU + 4096;     // 128
    float* sbc  = sbg + 128;     // 64
    float* sWo1 = sbc + 64;      // [64][64]
    float* sWo2 = sWo1 + 4096;   // [64][12]
    float* sbo1 = sWo2 + 768;    // 64
    float* sbo2 = sbo1 + 64;     // 12

    const float* Wg = (LAYER == 0) ? g_Wg1 : g_Wg2;
    const float* Wc = (LAYER == 0) ? g_Wc1 : g_Wc2;

    int tid = threadIdx.x;  // 512
    for (int i = tid; i < 16384; i += 512) sWg[i] = Wg[i];
    for (int i = tid; i < 8192; i += 512)  sWc[i] = Wc[i];
    for (int i = tid; i < 4096; i += 512)  sSt[i] = 0.f;
    if (tid < 128) sbg[tid] = bg[tid];
    if (tid < 64)  sbc[tid] = bc[tid];
    if (FINAL) {
        for (int i = tid; i < 4096; i += 512) sWo1[i] = Wo1[i];
        for (int i = tid; i < 768; i += 512)  sWo2[i] = Wo2[i];   // FIX: was `if (tid<768)` with 512 threads -> rows 42..63 garbage
        if (tid < 64)  sbo1[tid] = bo1[tid];
        if (tid < 12)  sbo2[tid] = bo2[tid];
    }
    __syncthreads();

    int row0 = blockIdx.x * 64;
    int tr = tid >> 4;   // 0..31 -> rows tr*2, tr*2+1
    int tc = tid & 15;   // 0..15
    int r0 = tr * 2;

    for (int t = 0; t < CK_P; t++) {
        // load x_t transposed into sZt[k][row]
        const float* src = g_buf + ((size_t)t * CK_BN + row0) * 64;
        for (int it = tid; it < 1024; it += 512) {
            int rr = it >> 4;
            int d4 = (it & 15) * 4;
            float4 v = *(const float4*)(src + rr * 64 + d4);
            sZt[(d4 + 0) * 64 + rr] = v.x;
            sZt[(d4 + 1) * 64 + rr] = v.y;
            sZt[(d4 + 2) * 64 + rr] = v.z;
            sZt[(d4 + 3) * 64 + rr] = v.w;
        }
        __syncthreads();

        // gate GEMM: [64 rows x 128 cols], K = 128 ( = [x | s] )
        float acc[2][8];
#pragma unroll
        for (int j = 0; j < 8; j++) { float bv = sbg[tc * 8 + j]; acc[0][j] = bv; acc[1][j] = bv; }
        {
            const float* aX = sZt + r0;
            const float* bW = sWg + tc * 8;
#pragma unroll 8
            for (int k = 0; k < 64; k++) {
                float2 a = *(const float2*)(aX + k * 64);
                float4 w0 = *(const float4*)(bW + k * 128);
                float4 w1 = *(const float4*)(bW + k * 128 + 4);
                GFMA(a.x, 0)
                GFMA(a.y, 1)
            }
            const float* aS = sSt + r0;
            const float* bW2 = sWg + 64 * 128 + tc * 8;
#pragma unroll 8
            for (int k = 0; k < 64; k++) {
                float2 a = *(const float2*)(aS + k * 64);
                float4 w0 = *(const float4*)(bW2 + k * 128);
                float4 w1 = *(const float4*)(bW2 + k * 128 + 4);
                GFMA(a.x, 0)
                GFMA(a.y, 1)
            }
        }
        // sigmoid; cols 0..63 = r -> stage r*s into sZt bottom; cols 64..127 = u -> sU
        if (tc < 8) {
#pragma unroll
            for (int i = 0; i < 2; i++)
#pragma unroll
                for (int j = 0; j < 8; j++) {
                    int col = tc * 8 + j, row = r0 + i;
                    float rv = sigm(acc[i][j]);
                    sZt[(64 + col) * 64 + row] = rv * sSt[col * 64 + row];
                }
        } else {
#pragma unroll
            for (int i = 0; i < 2; i++)
#pragma unroll
                for (int j = 0; j < 8; j++) {
                    int col = tc * 8 + j - 64, row = r0 + i;
                    sU[col * 64 + row] = sigm(acc[i][j]);
                }
        }
        __syncthreads();

        // candidate GEMM: [64 x 64], K = 128 ( = [x | r*s] )
        float acc2[2][4];
#pragma unroll
        for (int j = 0; j < 4; j++) { float bv = sbc[tc * 4 + j]; acc2[0][j] = bv; acc2[1][j] = bv; }
        {
            const float* aZ = sZt + r0;
            const float* bC = sWc + tc * 4;
#pragma unroll 8
            for (int k = 0; k < 128; k++) {
                float2 a = *(const float2*)(aZ + k * 64);
                float4 w = *(const float4*)(bC + k * 64);
                CFMA(a.x, 0)
                CFMA(a.y, 1)
            }
        }
        // state update: new = c + u*(s - c)
#pragma unroll
        for (int i = 0; i < 2; i++) {
            int row = r0 + i;
            float4 nv;
            float* nvp = &nv.x;
#pragma unroll
            for (int j = 0; j < 4; j++) {
                int col = tc * 4 + j;
                float cv = tanh_f(acc2[i][j]);
                float u = sU[col * 64 + row];
                float s = sSt[col * 64 + row];
                float v = fmaf(u, s - cv, cv);
                sSt[col * 64 + row] = v;
                nvp[j] = v;
            }
            if (!FINAL) {
                *(float4*)(g_buf + ((size_t)t * CK_BN + row0 + row) * 64 + tc * 4) = nv;
            }
        }
        __syncthreads();
    }

    if (FINAL) {
        // o1 = relu(h @ Wo1 + bo1): [64 x 64], K = 64
        float acc2[2][4];
#pragma unroll
        for (int j = 0; j < 4; j++) { float bv = sbo1[tc * 4 + j]; acc2[0][j] = bv; acc2[1][j] = bv; }
        {
            const float* aS = sSt + r0;
            const float* bC = sWo1 + tc * 4;
#pragma unroll 8
            for (int k = 0; k < 64; k++) {
                float2 a = *(const float2*)(aS + k * 64);
                float4 w = *(const float4*)(bC + k * 64);
                CFMA(a.x, 0)
                CFMA(a.y, 1)
            }
        }
#pragma unroll
        for (int i = 0; i < 2; i++)
#pragma unroll
            for (int j = 0; j < 4; j++)
                sZt[(tc * 4 + j) * 64 + (r0 + i)] = fmaxf(acc2[i][j], 0.f);
        __syncthreads();

        // y = o1 @ Wo2 + bo2 -> out[b][q][n]
        for (int idx = tid; idx < 64 * 12; idx += 512) {
            int row = idx / 12, q = idx % 12;
            float a = sbo2[q];
#pragma unroll 16
            for (int k = 0; k < 64; k++) a = fmaf(sZt[k * 64 + row], sWo2[k * 12 + q], a);
            int rowg = row0 + row;
            int b = rowg >> 10, n = rowg & 1023;
            out[((size_t)b * CK_Q + q) * CK_N + n] = a;
        }
    }
}

// ---------------------------------------------------------------- launch
extern "C" void kernel_launch(void* const* d_in, const int* in_sizes, int n_in,
                              void* d_out, int out_size) {
    const float* X     = (const float*)d_in[0];
    const float* SE    = (const float*)d_in[3];
    const float* W_se1 = (const float*)d_in[4];
    const float* b_se1 = (const float*)d_in[5];
    const float* W_se2 = (const float*)d_in[6];
    const float* b_se2 = (const float*)d_in[7];
    const float* W_te1 = (const float*)d_in[8];
    const float* b_te1 = (const float*)d_in[9];
    const float* W_te2 = (const float*)d_in[10];
    const float* b_te2 = (const float*)d_in[11];
    const float* W_in1 = (const float*)d_in[12];
    const float* b_in1 = (const float*)d_in[13];
    const float* W_in2 = (const float*)d_in[14];
    const float* b_in2 = (const float*)d_in[15];
    const float* Wg1   = (const float*)d_in[16];
    const float* bg1   = (const float*)d_in[17];
    const float* Wc1   = (const float*)d_in[18];
    const float* bc1   = (const float*)d_in[19];
    const float* Wg2   = (const float*)d_in[20];
    const float* bg2   = (const float*)d_in[21];
    const float* Wc2   = (const float*)d_in[22];
    const float* bc2   = (const float*)d_in[23];
    const float* W_o1  = (const float*)d_in[24];
    const float* b_o1  = (const float*)d_in[25];
    const float* W_o2  = (const float*)d_in[26];
    const float* b_o2  = (const float*)d_in[27];
    const int*   TE    = (const int*)d_in[28];
    float* out = (float*)d_out;

    size_t smem = (size_t)(16384 + 8192 + 8192 + 4096 + 4096 + 128 + 64 +
                           4096 + 768 + 64 + 16) * sizeof(float);
    cudaFuncSetAttribute(gru_k<0, false>, cudaFuncAttributeMaxDynamicSharedMemorySize, (int)smem);
    cudaFuncSetAttribute(gru_k<1, true>,  cudaFuncAttributeMaxDynamicSharedMemorySize, (int)smem);

    fold_k<<<64, 256>>>(Wg1, Wc1, Wg2, Wc2);
    se_k<<<CK_N, 64>>>(SE, W_se1, b_se1, W_se2, b_se2);
    te_k<<<CK_B * CK_P, 64>>>(TE, W_te1, b_te1, W_te2, b_te2);
    xe_k<<<(CK_P * CK_BN) / 128, 128>>>(X, W_in1, b_in1, W_in2, b_in2);
    gru_k<0, false><<<CK_BN / 64, 512, smem>>>(bg1, bc1, nullptr, nullptr, nullptr, nullptr, nullptr);
    gru_k<1, true><<<CK_BN / 64, 512, smem>>>(bg2, bc2, W_o1, b_o1, W_o2, b_o2, out);
}

// round 8
// speedup vs baseline: 1.6795x; 1.0821x over previous
#include <cuda_runtime.h>

#define CK_B 64
#define CK_P 12
#define CK_Q 12
#define CK_N 1024
#define CK_D 64
#define CK_BN (CK_B*CK_N)   // 65536 rows

// Scratch: [t][b][n][d]. Xe written here, layer1 overwrites in place with seq1.
__device__ float g_buf[(size_t)CK_P * CK_BN * CK_D];
__device__ float g_se2[CK_N * CK_D];
__device__ float g_te2[CK_B * CK_P * CK_D];
// Folded weights: Weff[k][j] = W[k][j] + W[k+128][j]  (support == identity)
__device__ float g_Wg1[128 * 128];
__device__ float g_Wc1[128 * 64];
__device__ float g_Wg2[128 * 128];
__device__ float g_Wc2[128 * 64];

typedef unsigned long long ull_t;

__device__ __forceinline__ float sigm(float x) {
    return __fdividef(1.0f, 1.0f + __expf(-x));
}
__device__ __forceinline__ float tanh_f(float x) {
    return __fdividef(2.0f, 1.0f + __expf(-2.0f * x)) - 1.0f;
}

// ---- packed fp32x2 primitives (Blackwell FFMA2; exact fp32, 2 FMA / instr) ----
__device__ __forceinline__ void ffma2(ull_t& d, ull_t a, ull_t b) {
    asm("fma.rn.f32x2 %0, %1, %2, %0;" : "+l"(d) : "l"(a), "l"(b));
}
__device__ __forceinline__ ull_t pack2(float x, float y) {
    ull_t r; asm("mov.b64 %0, {%1, %2};" : "=l"(r) : "f"(x), "f"(y)); return r;
}
__device__ __forceinline__ float2 unpack2(ull_t v) {
    float2 r; asm("mov.b64 {%0, %1}, %2;" : "=f"(r.x), "=f"(r.y) : "l"(v)); return r;
}

// ---------------------------------------------------------------- weight fold
__global__ void fold_k(const float* __restrict__ Wg1, const float* __restrict__ Wc1,
                       const float* __restrict__ Wg2, const float* __restrict__ Wc2) {
    int i = blockIdx.x * 256 + threadIdx.x;
    if (i < 128 * 128) {
        g_Wg1[i] = Wg1[i] + Wg1[i + 128 * 128];
        g_Wg2[i] = Wg2[i] + Wg2[i + 128 * 128];
    }
    if (i < 128 * 64) {
        g_Wc1[i] = Wc1[i] + Wc1[i + 128 * 64];
        g_Wc2[i] = Wc2[i] + Wc2[i + 128 * 64];
    }
}

// ---------------------------------------------------------------- SE embedding
__global__ void se_k(const float* __restrict__ SE, const float* __restrict__ W1,
                     const float* __restrict__ b1, const float* __restrict__ W2,
                     const float* __restrict__ b2) {
    __shared__ float srow[64];
    __shared__ float h[64];
    int n = blockIdx.x, d = threadIdx.x;
    srow[d] = SE[n * 64 + d];
    __syncthreads();
    float a = b1[d];
#pragma unroll 16
    for (int k = 0; k < 64; k++) a = fmaf(srow[k], W1[k * 64 + d], a);
    h[d] = fmaxf(a, 0.f);
    __syncthreads();
    float o = b2[d];
#pragma unroll 16
    for (int k = 0; k < 64; k++) o = fmaf(h[k], W2[k * 64 + d], o);
    g_se2[n * 64 + d] = o;
}

// ---------------------------------------------------------------- TE embedding
__global__ void te_k(const int* __restrict__ TE, const float* __restrict__ W1,
                     const float* __restrict__ b1, const float* __restrict__ W2,
                     const float* __restrict__ b2) {
    __shared__ float h[64];
    int bp = blockIdx.x;          // b*12 + p
    int b = bp / 12, p = bp % 12, d = threadIdx.x;
    int dow = TE[(b * 24 + p) * 2 + 0];
    int tod = TE[(b * 24 + p) * 2 + 1];
    float a = W1[dow * 64 + d] + W1[(7 + tod) * 64 + d] + b1[d];
    h[d] = fmaxf(a, 0.f);
    __syncthreads();
    float o = b2[d];
#pragma unroll 16
    for (int k = 0; k < 64; k++) o = fmaf(h[k], W2[k * 64 + d], o);
    g_te2[bp * 64 + d] = o;
}

// ---------------------------------------------------------------- FC_X_in + STE
// 256 threads: thread = 4 positions x 16 cols. 4x less SMEM W2 traffic per
// output than 1x64, and each W2 load feeds 4 packed FMAs. FFMA2 inner loop.
__global__ void __launch_bounds__(256) xe_k(
        const float* __restrict__ X, const float* __restrict__ W1,
        const float* __restrict__ b1, const float* __restrict__ W2,
        const float* __restrict__ b2) {
    __shared__ float sW2[64 * 64];
    __shared__ float sw1[64], sb1[64], sb2[64];
    int tid = threadIdx.x;  // 256
    for (int i = tid; i < 4096; i += 256) sW2[i] = W2[i];
    if (tid < 64) { sw1[tid] = W1[tid]; sb1[tid] = b1[tid]; sb2[tid] = b2[tid]; }
    __syncthreads();

    int cg = tid & 3;        // col group: cols cg*16 .. cg*16+15
    int pt = tid >> 2;       // 0..63 position-group within block
    size_t pbase = (size_t)blockIdx.x * 256 + (size_t)pt * 4;  // 4 consecutive positions

    // gather the 4 scalar x values (positions in g_buf order: pos = t*BN + b*N + n)
    float xv[4];
    int tt[4], bb[4], nn[4];
#pragma unroll
    for (int pp = 0; pp < 4; pp++) {
        size_t pos = pbase + pp;
        int t = (int)(pos >> 16);            // / CK_BN
        int r = (int)(pos & 65535);
        int b = r >> 10, n = r & 1023;
        tt[pp] = t; bb[pp] = b; nn[pp] = n;
        xv[pp] = X[(b * CK_P + t) * CK_N + n];
    }

    ull_t acc[4][8];   // [pos][col-pair], cols cg*16 + 2jp, +1
    {
        const ull_t* b2p = (const ull_t*)(sb2 + cg * 16);
#pragma unroll
        for (int jp = 0; jp < 8; jp++) {
            ull_t bv = b2p[jp];
#pragma unroll
            for (int pp = 0; pp < 4; pp++) acc[pp][jp] = bv;
        }
    }

#pragma unroll 4
    for (int d = 0; d < 64; d++) {
        float w1v = sw1[d], b1v = sb1[d];
        ull_t hx[4];
#pragma unroll
        for (int pp = 0; pp < 4; pp++) {
            float hv = fmaxf(fmaf(xv[pp], w1v, b1v), 0.f);
            hx[pp] = pack2(hv, hv);
        }
        const ulonglong2* wp = (const ulonglong2*)(sW2 + d * 64 + cg * 16);
        ulonglong2 wa = wp[0], wb = wp[1], wc = wp[2], wd = wp[3];
#pragma unroll
        for (int pp = 0; pp < 4; pp++) {
            ffma2(acc[pp][0], hx[pp], wa.x); ffma2(acc[pp][1], hx[pp], wa.y);
            ffma2(acc[pp][2], hx[pp], wb.x); ffma2(acc[pp][3], hx[pp], wb.y);
            ffma2(acc[pp][4], hx[pp], wc.x); ffma2(acc[pp][5], hx[pp], wc.y);
            ffma2(acc[pp][6], hx[pp], wd.x); ffma2(acc[pp][7], hx[pp], wd.y);
        }
    }

#pragma unroll
    for (int pp = 0; pp < 4; pp++) {
        const float* se = g_se2 + nn[pp] * 64 + cg * 16;
        const float* te = g_te2 + (bb[pp] * CK_P + tt[pp]) * 64 + cg * 16;
        float* outp = g_buf + (pbase + pp) * 64 + cg * 16;
#pragma unroll
        for (int q = 0; q < 4; q++) {   // 4 float4 stores = 16 cols
            float2 v0 = unpack2(acc[pp][q * 2 + 0]);
            float2 v1 = unpack2(acc[pp][q * 2 + 1]);
            float4 v;
            v.x = v0.x + se[q * 4 + 0] + te[q * 4 + 0];
            v.y = v0.y + se[q * 4 + 1] + te[q * 4 + 1];
            v.z = v1.x + se[q * 4 + 2] + te[q * 4 + 2];
            v.w = v1.y + se[q * 4 + 3] + te[q * 4 + 3];
            *(float4*)(outp + q * 4) = v;
        }
    }
}

// ---------------------------------------------------------------- DCGRU layer
// Persistent per-tile scan: block owns 64 rows, runs all 12 time steps with
// weights + state resident in SMEM. Inner GEMMs use packed fp32x2 FMA
// (column-pair packing: W loads directly as 64-bit pairs, A broadcast packed).
template<int LAYER, bool FINAL>
__global__ void __launch_bounds__(512, 1) gru_k(
        const float* __restrict__ bg, const float* __restrict__ bc,
        const float* __restrict__ Wo1, const float* __restrict__ bo1,
        const float* __restrict__ Wo2, const float* __restrict__ bo2,
        float* __restrict__ out) {
    extern __shared__ float sm[];
    float* sWg  = sm;            // [128][128]
    float* sWc  = sWg + 16384;   // [128][64]
    float* sZt  = sWc + 8192;    // [128][64]  k-major: rows 0..63 = x_t, 64..127 = r*s
    float* sSt  = sZt + 8192;    // [64][64]   state, k-major
    float* sU   = sSt + 4096;    // [64][64]   update gate
    float* sbg  = sU + 4096;     // 128
    float* sbc  = sbg + 128;     // 64
    float* sWo1 = sbc + 64;      // [64][64]
    float* sWo2 = sWo1 + 4096;   // [64][12]
    float* sbo1 = sWo2 + 768;    // 64
    float* sbo2 = sbo1 + 64;     // 12

    const float* Wg = (LAYER == 0) ? g_Wg1 : g_Wg2;
    const float* Wc = (LAYER == 0) ? g_Wc1 : g_Wc2;

    int tid = threadIdx.x;  // 512
    for (int i = tid; i < 16384; i += 512) sWg[i] = Wg[i];
    for (int i = tid; i < 8192; i += 512)  sWc[i] = Wc[i];
    for (int i = tid; i < 4096; i += 512)  sSt[i] = 0.f;
    if (tid < 128) sbg[tid] = bg[tid];
    if (tid < 64)  sbc[tid] = bc[tid];
    if (FINAL) {
        for (int i = tid; i < 4096; i += 512) sWo1[i] = Wo1[i];
        for (int i = tid; i < 768; i += 512)  sWo2[i] = Wo2[i];
        if (tid < 64)  sbo1[tid] = bo1[tid];
        if (tid < 12)  sbo2[tid] = bo2[tid];
    }
    __syncthreads();

    int row0 = blockIdx.x * 64;
    int tr = tid >> 4;   // 0..31 -> rows tr*2, tr*2+1
    int tc = tid & 15;   // 0..15
    int r0 = tr * 2;

    for (int t = 0; t < CK_P; t++) {
        // load x_t transposed into sZt[k][row]
        const float* src = g_buf + ((size_t)t * CK_BN + row0) * 64;
        for (int it = tid; it < 1024; it += 512) {
            int rr = it >> 4;
            int d4 = (it & 15) * 4;
            float4 v = *(const float4*)(src + rr * 64 + d4);
            sZt[(d4 + 0) * 64 + rr] = v.x;
            sZt[(d4 + 1) * 64 + rr] = v.y;
            sZt[(d4 + 2) * 64 + rr] = v.z;
            sZt[(d4 + 3) * 64 + rr] = v.w;
        }
        __syncthreads();

        // gate GEMM: [64 rows x 128 cols], K = 128 ( = [x | s] ), fp32x2 packed
        ull_t accg[2][4];
        {
            const ull_t* bgp = (const ull_t*)(sbg + tc * 8);
#pragma unroll
            for (int jp = 0; jp < 4; jp++) { accg[0][jp] = bgp[jp]; accg[1][jp] = bgp[jp]; }
        }
        {
            const float* aX = sZt + r0;
            const float* bW = sWg + tc * 8;
#pragma unroll 8
            for (int k = 0; k < 64; k++) {
                float2 a = *(const float2*)(aX + k * 64);
                ull_t ax = pack2(a.x, a.x), ay = pack2(a.y, a.y);
                const ulonglong2* wp = (const ulonglong2*)(bW + k * 128);
                ulonglong2 w01 = wp[0], w23 = wp[1];
                ffma2(accg[0][0], ax, w01.x); ffma2(accg[0][1], ax, w01.y);
                ffma2(accg[0][2], ax, w23.x); ffma2(accg[0][3], ax, w23.y);
                ffma2(accg[1][0], ay, w01.x); ffma2(accg[1][1], ay, w01.y);
                ffma2(accg[1][2], ay, w23.x); ffma2(accg[1][3], ay, w23.y);
            }
            const float* aS = sSt + r0;
            const float* bW2 = sWg + 64 * 128 + tc * 8;
#pragma unroll 8
            for (int k = 0; k < 64; k++) {
                float2 a = *(const float2*)(aS + k * 64);
                ull_t ax = pack2(a.x, a.x), ay = pack2(a.y, a.y);
                const ulonglong2* wp = (const ulonglong2*)(bW2 + k * 128);
                ulonglong2 w01 = wp[0], w23 = wp[1];
                ffma2(accg[0][0], ax, w01.x); ffma2(accg[0][1], ax, w01.y);
                ffma2(accg[0][2], ax, w23.x); ffma2(accg[0][3], ax, w23.y);
                ffma2(accg[1][0], ay, w01.x); ffma2(accg[1][1], ay, w01.y);
                ffma2(accg[1][2], ay, w23.x); ffma2(accg[1][3], ay, w23.y);
            }
        }
        float vals[2][8];
#pragma unroll
        for (int i = 0; i < 2; i++)
#pragma unroll
            for (int jp = 0; jp < 4; jp++) {
                float2 v = unpack2(accg[i][jp]);
                vals[i][jp * 2 + 0] = v.x;
                vals[i][jp * 2 + 1] = v.y;
            }
        // sigmoid; cols 0..63 = r -> stage r*s into sZt bottom; cols 64..127 = u -> sU
        if (tc < 8) {
#pragma unroll
            for (int i = 0; i < 2; i++)
#pragma unroll
                for (int j = 0; j < 8; j++) {
                    int col = tc * 8 + j, row = r0 + i;
                    float rv = sigm(vals[i][j]);
                    sZt[(64 + col) * 64 + row] = rv * sSt[col * 64 + row];
                }
        } else {
#pragma unroll
            for (int i = 0; i < 2; i++)
#pragma unroll
                for (int j = 0; j < 8; j++) {
                    int col = tc * 8 + j - 64, row = r0 + i;
                    sU[col * 64 + row] = sigm(vals[i][j]);
                }
        }
        __syncthreads();

        // candidate GEMM: [64 x 64], K = 128 ( = [x | r*s] ), fp32x2 packed
        ull_t accc[2][2];
        {
            const ull_t* bcp = (const ull_t*)(sbc + tc * 4);
            accc[0][0] = bcp[0]; accc[0][1] = bcp[1];
            accc[1][0] = bcp[0]; accc[1][1] = bcp[1];
        }
        {
            const float* aZ = sZt + r0;
            const float* bC = sWc + tc * 4;
#pragma unroll 8
            for (int k = 0; k < 128; k++) {
                float2 a = *(const float2*)(aZ + k * 64);
                ull_t ax = pack2(a.x, a.x), ay = pack2(a.y, a.y);
                ulonglong2 w = *(const ulonglong2*)(bC + k * 64);
                ffma2(accc[0][0], ax, w.x); ffma2(accc[0][1], ax, w.y);
                ffma2(accc[1][0], ay, w.x); ffma2(accc[1][1], ay, w.y);
            }
        }
        // state update: new = c + u*(s - c)
#pragma unroll
        for (int i = 0; i < 2; i++) {
            int row = r0 + i;
            float2 c0 = unpack2(accc[i][0]);
            float2 c1 = unpack2(accc[i][1]);
            float cvv[4] = {c0.x, c0.y, c1.x, c1.y};
            float4 nv;
            float* nvp = &nv.x;
#pragma unroll
            for (int j = 0; j < 4; j++) {
                int col = tc * 4 + j;
                float cv = tanh_f(cvv[j]);
                float u = sU[col * 64 + row];
                float s = sSt[col * 64 + row];
                float v = fmaf(u, s - cv, cv);
                sSt[col * 64 + row] = v;
                nvp[j] = v;
            }
            if (!FINAL) {
                *(float4*)(g_buf + ((size_t)t * CK_BN + row0 + row) * 64 + tc * 4) = nv;
            }
        }
        __syncthreads();
    }

    if (FINAL) {
        // o1 = relu(h @ Wo1 + bo1): [64 x 64], K = 64, fp32x2 packed
        ull_t acco[2][2];
        {
            const ull_t* bop = (const ull_t*)(sbo1 + tc * 4);
            acco[0][0] = bop[0]; acco[0][1] = bop[1];
            acco[1][0] = bop[0]; acco[1][1] = bop[1];
        }
        {
            const float* aS = sSt + r0;
            const float* bC = sWo1 + tc * 4;
#pragma unroll 8
            for (int k = 0; k < 64; k++) {
                float2 a = *(const float2*)(aS + k * 64);
                ull_t ax = pack2(a.x, a.x), ay = pack2(a.y, a.y);
                ulonglong2 w = *(const ulonglong2*)(bC + k * 64);
                ffma2(acco[0][0], ax, w.x); ffma2(acco[0][1], ax, w.y);
                ffma2(acco[1][0], ay, w.x); ffma2(acco[1][1], ay, w.y);
            }
        }
#pragma unroll
        for (int i = 0; i < 2; i++) {
            float2 v0 = unpack2(acco[i][0]);
            float2 v1 = unpack2(acco[i][1]);
            float vv[4] = {v0.x, v0.y, v1.x, v1.y};
#pragma unroll
            for (int j = 0; j < 4; j++)
                sZt[(tc * 4 + j) * 64 + (r0 + i)] = fmaxf(vv[j], 0.f);
        }
        __syncthreads();

        // y = o1 @ Wo2 + bo2 -> out[b][q][n]
        for (int idx = tid; idx < 64 * 12; idx += 512) {
            int row = idx / 12, q = idx % 12;
            float a = sbo2[q];
#pragma unroll 16
            for (int k = 0; k < 64; k++) a = fmaf(sZt[k * 64 + row], sWo2[k * 12 + q], a);
            int rowg = row0 + row;
            int b = rowg >> 10, n = rowg & 1023;
            out[((size_t)b * CK_Q + q) * CK_N + n] = a;
        }
    }
}

// ---------------------------------------------------------------- launch
extern "C" void kernel_launch(void* const* d_in, const int* in_sizes, int n_in,
                              void* d_out, int out_size) {
    const float* X     = (const float*)d_in[0];
    const float* SE    = (const float*)d_in[3];
    const float* W_se1 = (const float*)d_in[4];
    const float* b_se1 = (const float*)d_in[5];
    const float* W_se2 = (const float*)d_in[6];
    const float* b_se2 = (const float*)d_in[7];
    const float* W_te1 = (const float*)d_in[8];
    const float* b_te1 = (const float*)d_in[9];
    const float* W_te2 = (const float*)d_in[10];
    const float* b_te2 = (const float*)d_in[11];
    const float* W_in1 = (const float*)d_in[12];
    const float* b_in1 = (const float*)d_in[13];
    const float* W_in2 = (const float*)d_in[14];
    const float* b_in2 = (const float*)d_in[15];
    const float* Wg1   = (const float*)d_in[16];
    const float* bg1   = (const float*)d_in[17];
    const float* Wc1   = (const float*)d_in[18];
    const float* bc1   = (const float*)d_in[19];
    const float* Wg2   = (const float*)d_in[20];
    const float* bg2   = (const float*)d_in[21];
    const float* Wc2   = (const float*)d_in[22];
    const float* bc2   = (const float*)d_in[23];
    const float* W_o1  = (const float*)d_in[24];
    const float* b_o1  = (const float*)d_in[25];
    const float* W_o2  = (const float*)d_in[26];
    const float* b_o2  = (const float*)d_in[27];
    const int*   TE    = (const int*)d_in[28];
    float* out = (float*)d_out;

    size_t smem = (size_t)(16384 + 8192 + 8192 + 4096 + 4096 + 128 + 64 +
                           4096 + 768 + 64 + 16) * sizeof(float);
    cudaFuncSetAttribute(gru_k<0, false>, cudaFuncAttributeMaxDynamicSharedMemorySize, (int)smem);
    cudaFuncSetAttribute(gru_k<1, true>,  cudaFuncAttributeMaxDynamicSharedMemorySize, (int)smem);

    fold_k<<<64, 256>>>(Wg1, Wc1, Wg2, Wc2);
    se_k<<<CK_N, 64>>>(SE, W_se1, b_se1, W_se2, b_se2);
    te_k<<<CK_B * CK_P, 64>>>(TE, W_te1, b_te1, W_te2, b_te2);
    xe_k<<<(CK_P * CK_BN) / 256, 256>>>(X, W_in1, b_in1, W_in2, b_in2);
    gru_k<0, false><<<CK_BN / 64, 512, smem>>>(bg1, bc1, nullptr, nullptr, nullptr, nullptr, nullptr);
    gru_k<1, true><<<CK_BN / 64, 512, smem>>>(bg2, bc2, W_o1, b_o1, W_o2, b_o2, out);
}